// round 5
// baseline (speedup 1.0000x reference)
#include <cuda_runtime.h>
#include <cuda_fp16.h>
#include <math.h>
#include <stdint.h>

#define NPTS 8192
#define NSRC 4096
#define DIM  256
#define TILE 128
#define NT   (NPTS / TILE)          // 64
#define NBLK (NT * (NT + 1) / 2)    // 2080 upper-triangle tile pairs
#define NCTA 148

// ---------------------------------------------------------------- scratch
__device__ float  g_sq[NPTS];
__device__ double g_colsum[DIM];
__device__ double g_sumsq;
__device__ float  g_c;              // exp2 scale: -1/(16*bw'*ln2)
__device__ double g_acc;
__device__ __half g_hi[NPTS * DIM];
__device__ __half g_lo[NPTS * DIM];

// ---------------------------------------------------------------- helpers
__device__ __forceinline__ uint32_t smem_u32(const void* p) {
    uint32_t a;
    asm("{ .reg .u64 t; cvta.to.shared.u64 t, %1; cvt.u32.u64 %0, t; }" : "=r"(a) : "l"(p));
    return a;
}
#define CP_ASYNC16(dst, src) \
    asm volatile("cp.async.ca.shared.global [%0], [%1], 16;" :: "r"(dst), "l"(src))
#define CP_COMMIT() asm volatile("cp.async.commit_group;" ::: "memory")
#define CP_WAIT1()  asm volatile("cp.async.wait_group 1;" ::: "memory")

#define LDSM_X4(r0, r1, r2, r3, a) \
    asm volatile("ldmatrix.sync.aligned.m8n8.x4.shared.b16 {%0,%1,%2,%3}, [%4];" \
        : "=r"(r0), "=r"(r1), "=r"(r2), "=r"(r3) : "r"(a))

#define MMA_F16(d, a, b0, b1) \
    asm volatile("mma.sync.aligned.m16n8k16.row.col.f32.f16.f16.f32 " \
        "{%0,%1,%2,%3}, {%4,%5,%6,%7}, {%8,%9}, {%0,%1,%2,%3};" \
        : "+f"((d)[0]), "+f"((d)[1]), "+f"((d)[2]), "+f"((d)[3]) \
        : "r"((a)[0]), "r"((a)[1]), "r"((a)[2]), "r"((a)[3]), "r"(b0), "r"(b1))

__device__ __forceinline__ const float* row_ptr(const float* src, const float* tgt, int i) {
    return (i < NSRC) ? (src + (size_t)i * DIM) : (tgt + (size_t)(i - NSRC) * DIM);
}

// decode linear tile id -> (bi, bj), bi <= bj
__device__ __forceinline__ void decode_tile(int b, int& bi_o, int& bj_o) {
    float fb = (float)b;
    int bi = (int)((2.0f * NT + 1.0f - sqrtf((2.0f * NT + 1.0f) * (2.0f * NT + 1.0f) - 8.0f * fb)) * 0.5f);
    if (bi < 0) bi = 0;
    if (bi >= NT) bi = NT - 1;
#define TRI_START(i) ((i) * NT - (i) * ((i) - 1) / 2)
    while (bi + 1 < NT && TRI_START(bi + 1) <= b) bi++;
    while (bi > 0 && TRI_START(bi) > b) bi--;
    bj_o = bi + (b - TRI_START(bi));
#undef TRI_START
    bi_o = bi;
}

// ---------------------------------------------------------------- prep kernels
__global__ void zero_kernel() {
    int t = threadIdx.x;
    if (t < DIM) g_colsum[t] = 0.0;
    if (t == 0) { g_sumsq = 0.0; g_acc = 0.0; }
}

// 128 blocks x 256 threads; block handles 64 rows (warp -> 8 rows).
// Fused: fp16 hi/lo split + per-row ||x||^2 + column sums.
__global__ void prep_kernel(const float* __restrict__ src, const float* __restrict__ tgt) {
    __shared__ float cs[DIM];
    int tid  = threadIdx.x;
    int wid  = tid >> 5;
    int lane = tid & 31;
    cs[tid] = 0.f;
    __syncthreads();

    float col_acc[8] = {0, 0, 0, 0, 0, 0, 0, 0};
    float sq_acc = 0.f;

    int rbase = blockIdx.x * 64 + wid * 8;
    for (int rr = 0; rr < 8; rr++) {
        int row = rbase + rr;
        const float4* p4 = (const float4*)row_ptr(src, tgt, row);
        float s = 0.f;
#pragma unroll
        for (int t = 0; t < 2; t++) {
            float4 v = p4[lane + t * 32];
            float x[4] = {v.x, v.y, v.z, v.w};
            uint32_t hb[4], lb[4];
#pragma unroll
            for (int k = 0; k < 4; k++) {
                s += x[k] * x[k];
                col_acc[t * 4 + k] += x[k];
                __half h = __float2half_rn(x[k]);
                float r = x[k] - __half2float(h);
                __half l = __float2half_rn(r);
                hb[k] = (uint32_t)__half_as_ushort(h);
                lb[k] = (uint32_t)__half_as_ushort(l);
            }
            size_t q = (size_t)row * 64 + lane + t * 32;   // uint2 index (4 halves)
            ((uint2*)g_hi)[q] = make_uint2(hb[0] | (hb[1] << 16), hb[2] | (hb[3] << 16));
            ((uint2*)g_lo)[q] = make_uint2(lb[0] | (lb[1] << 16), lb[2] | (lb[3] << 16));
        }
#pragma unroll
        for (int o = 16; o > 0; o >>= 1) s += __shfl_xor_sync(0xffffffffu, s, o);
        if (lane == 0) g_sq[row] = s;
        if (lane == 0) sq_acc += s;
    }
    if (lane == 0) atomicAdd(&g_sumsq, (double)sq_acc);

    // fold warp-local column sums into block smem, then one atomic per column
#pragma unroll
    for (int t = 0; t < 2; t++)
#pragma unroll
        for (int k = 0; k < 4; k++)
            atomicAdd(&cs[t * 128 + lane * 4 + k], col_acc[t * 4 + k]);
    __syncthreads();
    atomicAdd(&g_colsum[tid], (double)cs[tid]);
}

__global__ void finalize_kernel() {
    __shared__ double red[DIM];
    int t = threadIdx.x;
    double c = g_colsum[t];
    red[t] = c * c;
    __syncthreads();
    for (int o = 128; o > 0; o >>= 1) {
        if (t < o) red[t] += red[t + o];
        __syncthreads();
    }
    if (t == 0) {
        double n = (double)NPTS;
        double sumL2 = 2.0 * n * g_sumsq - 2.0 * red[0];
        double bw = sumL2 / (n * n - n) / 4.0;   // / KERNEL_MUL^(KERNEL_NUM//2)
        g_c = (float)(-1.0 / (16.0 * bw * 0.6931471805599453));
    }
}

// ---------------------------------------------------------------- main tile kernel
// smem arrays per stage: A_hi, B_hi, B_lo; each 128 rows x 80B (32 fp16 + pad)
#define STRIDE_B    80
#define ARR_BYTES   (128 * STRIDE_B)        // 10240
#define STAGE_BYTES (3 * ARR_BYTES)         // 30720
#define NSTAGE      3
#define DYN_SMEM    (NSTAGE * STAGE_BYTES)  // 92160

__global__ void __launch_bounds__(256, 1)
mmd_mma_kernel() {
    extern __shared__ char dsmem[];
    __shared__ float red[256];
    __shared__ float sqa_s[TILE];
    __shared__ float sqb_s[TILE];

    uint32_t dyn_u = smem_u32(dsmem);
    int tid  = threadIdx.x;
    int wid  = tid >> 5;
    int lane = tid & 31;
    int wm   = wid & 1;       // 2 warp-rows of 64
    int wn   = wid >> 1;      // 4 warp-cols of 32
    int b0   = blockIdx.x;

    // ---- load-side state (tile whose chunks are being fetched) ----
    int l_li = -1;
    bool l_valid = false;
    const char* lbase[3];

#define ISSUE(g) do { \
    int _li = (g) >> 3; \
    if (_li != l_li) { \
        l_li = _li; \
        int _tb = b0 + _li * NCTA; \
        if (_tb < NBLK) { \
            int _bi, _bj; decode_tile(_tb, _bi, _bj); \
            lbase[0] = (const char*)(g_hi + (size_t)_bi * TILE * DIM); \
            lbase[1] = (const char*)(g_hi + (size_t)_bj * TILE * DIM); \
            lbase[2] = (const char*)(g_lo + (size_t)_bj * TILE * DIM); \
            l_valid = true; \
        } else l_valid = false; \
    } \
    if (l_valid) { \
        int _c = (g) & 7; \
        uint32_t _st = dyn_u + ((g) % NSTAGE) * STAGE_BYTES; \
        _Pragma("unroll") \
        for (int _i = 0; _i < 6; _i++) { \
            int _arr = _i >> 1; \
            int _rem = tid + (_i & 1) * 256; \
            int _row = _rem >> 2; \
            int _q   = _rem & 3; \
            const char* _sp = lbase[_arr] + (size_t)_row * 512 + _c * 64 + _q * 16; \
            uint32_t _dst = _st + _arr * ARR_BYTES + _row * STRIDE_B + _q * 16; \
            CP_ASYNC16(_dst, _sp); \
        } \
    } \
    CP_COMMIT(); \
} while (0)

    // ldmatrix lane-address components
    int a_m    = lane >> 3;
    int a_rofs = ((a_m & 1) << 3) + (lane & 7);
    int a_koff = (a_m >> 1) << 4;
    int b_nofs = ((a_m >> 1) << 3) + (lane & 7);
    int b_koff = (a_m & 1) << 4;

    int ntiles = (NBLK - b0 + NCTA - 1) / NCTA;

    ISSUE(0);
    ISSUE(1);

    for (int li = 0; li < ntiles; li++) {
        int tb = b0 + li * NCTA;
        int bi, bj;
        decode_tile(tb, bi, bj);
        int row0 = bi * TILE;
        int col0 = bj * TILE;

        float acc[4][4][4];
#pragma unroll
        for (int mi = 0; mi < 4; mi++)
#pragma unroll
            for (int ni = 0; ni < 4; ni++)
#pragma unroll
                for (int e = 0; e < 4; e++) acc[mi][ni][e] = 0.f;

        for (int c = 0; c < 8; c++) {
            int g = li * 8 + c;
            CP_WAIT1();
            __syncthreads();
            if (c == 0 && tid < TILE) {
                sqa_s[tid] = g_sq[row0 + tid];
                sqb_s[tid] = g_sq[col0 + tid];
            }
            ISSUE(g + 2);

            uint32_t stage_u = dyn_u + (g % NSTAGE) * STAGE_BYTES;
#pragma unroll
            for (int ks = 0; ks < 2; ks++) {
                uint32_t Ah[4][4], Bh[2][4], Bl[2][4];
#pragma unroll
                for (int mi = 0; mi < 4; mi++) {
                    int r = wm * 64 + mi * 16 + a_rofs;
                    uint32_t ad = stage_u + r * STRIDE_B + ks * 32 + a_koff;
                    LDSM_X4(Ah[mi][0], Ah[mi][1], Ah[mi][2], Ah[mi][3], ad);
                }
#pragma unroll
                for (int pi = 0; pi < 2; pi++) {
                    int nl = wn * 32 + pi * 16 + b_nofs;
                    uint32_t bd = stage_u + ARR_BYTES + nl * STRIDE_B + ks * 32 + b_koff;
                    LDSM_X4(Bh[pi][0], Bh[pi][1], Bh[pi][2], Bh[pi][3], bd);
                    LDSM_X4(Bl[pi][0], Bl[pi][1], Bl[pi][2], Bl[pi][3], bd + ARR_BYTES);
                }
#pragma unroll
                for (int mi = 0; mi < 4; mi++) {
#pragma unroll
                    for (int ni = 0; ni < 4; ni++) {
                        int pi = ni >> 1, h = (ni & 1) * 2;
                        MMA_F16(acc[mi][ni], Ah[mi], Bh[pi][h], Bh[pi][h + 1]);
                        MMA_F16(acc[mi][ni], Ah[mi], Bl[pi][h], Bl[pi][h + 1]);
                    }
                }
            }
            __syncthreads();   // stage (g%3) free for refill
        }

        // epilogue (next tile's chunk 0/1 loads already in flight)
        float cexp = g_c;
        int rlo = lane >> 2;
        int cl0 = (lane & 3) * 2;
        float s = 0.f;
#pragma unroll
        for (int mi = 0; mi < 4; mi++) {
            float sqr0 = sqa_s[wm * 64 + mi * 16 + rlo];
            float sqr1 = sqa_s[wm * 64 + mi * 16 + rlo + 8];
#pragma unroll
            for (int ni = 0; ni < 4; ni++) {
                float sqc0 = sqb_s[wn * 32 + ni * 8 + cl0];
                float sqc1 = sqb_s[wn * 32 + ni * 8 + cl0 + 1];
#pragma unroll
                for (int e = 0; e < 4; e++) {
                    float sr = (e >= 2) ? sqr1 : sqr0;
                    float sc = (e & 1) ? sqc1 : sqc0;
                    float L2 = fmaxf(sr + sc - 2.f * acc[mi][ni][e], 0.f);
                    float u;
                    asm("ex2.approx.ftz.f32 %0, %1;" : "=f"(u) : "f"(L2 * cexp));
                    float u2 = u * u, u4 = u2 * u2, u8 = u4 * u4;
                    s += u + u2 + u4 + u8 + u8 * u8;
                }
            }
        }

        red[tid] = s;
        __syncthreads();
#pragma unroll
        for (int o = 128; o > 0; o >>= 1) {
            if (tid < o) red[tid] += red[tid + o];
            __syncthreads();
        }
        if (tid == 0) {
            float w  = (bi == bj) ? 1.f : 2.f;
            float sr = (row0 < NSRC) ? 1.f : -1.f;
            float sc = (col0 < NSRC) ? 1.f : -1.f;
            atomicAdd(&g_acc, (double)(red[0] * w * sr * sc));
        }
    }
}

__global__ void writeout_kernel(float* out) {
    out[0] = (float)(g_acc / ((double)NSRC * (double)NSRC));
}

// ---------------------------------------------------------------- launch
extern "C" void kernel_launch(void* const* d_in, const int* in_sizes, int n_in,
                              void* d_out, int out_size) {
    const float* src = (const float*)d_in[0];
    const float* tgt = (const float*)d_in[1];
    float* out = (float*)d_out;

    cudaFuncSetAttribute(mmd_mma_kernel, cudaFuncAttributeMaxDynamicSharedMemorySize, DYN_SMEM);

    zero_kernel<<<1, 256>>>();
    prep_kernel<<<NPTS / 64, 256>>>(src, tgt);     // split + norms + colsums fused
    finalize_kernel<<<1, 256>>>();
    mmd_mma_kernel<<<NCTA, 256, DYN_SMEM>>>();
    writeout_kernel<<<1, 1>>>(out);
}

// round 6
// speedup vs baseline: 1.1000x; 1.1000x over previous
#include <cuda_runtime.h>
#include <cuda_fp16.h>
#include <math.h>
#include <stdint.h>

#define NPTS 8192
#define NSRC 4096
#define DIM  256
#define TILE 128
#define NT   (NPTS / TILE)          // 64
#define NBLK (NT * (NT + 1) / 2)    // 2080 upper-triangle tile pairs

// ---------------------------------------------------------------- scratch
__device__ float  g_sq[NPTS];
__device__ double g_colsum[DIM];
__device__ double g_sumsq;
__device__ float  g_c;              // exp2 scale: -1/(16*bw'*ln2)
__device__ double g_acc;
__device__ __half g_hi[NPTS * DIM];
__device__ __half g_lo[NPTS * DIM];

// ---------------------------------------------------------------- helpers
__device__ __forceinline__ uint32_t smem_u32(const void* p) {
    uint32_t a;
    asm("{ .reg .u64 t; cvta.to.shared.u64 t, %1; cvt.u32.u64 %0, t; }" : "=r"(a) : "l"(p));
    return a;
}
#define CP_ASYNC16(dst, src) \
    asm volatile("cp.async.ca.shared.global [%0], [%1], 16;" :: "r"(dst), "l"(src))
#define CP_COMMIT() asm volatile("cp.async.commit_group;" ::: "memory")
#define CP_WAIT1()  asm volatile("cp.async.wait_group 1;" ::: "memory")

#define LDSM_X4(r0, r1, r2, r3, a) \
    asm volatile("ldmatrix.sync.aligned.m8n8.x4.shared.b16 {%0,%1,%2,%3}, [%4];" \
        : "=r"(r0), "=r"(r1), "=r"(r2), "=r"(r3) : "r"(a))

#define MMA_F16(d, a, b0, b1) \
    asm volatile("mma.sync.aligned.m16n8k16.row.col.f32.f16.f16.f32 " \
        "{%0,%1,%2,%3}, {%4,%5,%6,%7}, {%8,%9}, {%0,%1,%2,%3};" \
        : "+f"((d)[0]), "+f"((d)[1]), "+f"((d)[2]), "+f"((d)[3]) \
        : "r"((a)[0]), "r"((a)[1]), "r"((a)[2]), "r"((a)[3]), "r"(b0), "r"(b1))

__device__ __forceinline__ const float* row_ptr(const float* src, const float* tgt, int i) {
    return (i < NSRC) ? (src + (size_t)i * DIM) : (tgt + (size_t)(i - NSRC) * DIM);
}

// ---------------------------------------------------------------- prep kernels
__global__ void zero_kernel() {
    int t = threadIdx.x;
    if (t < DIM) g_colsum[t] = 0.0;
    if (t == 0) { g_sumsq = 0.0; g_acc = 0.0; }
}

// 128 blocks x 256 threads; block handles 64 rows (warp -> 8 rows).
// Fused: fp16 hi/lo split + per-row ||x||^2 + column sums.
__global__ void prep_kernel(const float* __restrict__ src, const float* __restrict__ tgt) {
    __shared__ float cs[DIM];
    int tid  = threadIdx.x;
    int wid  = tid >> 5;
    int lane = tid & 31;
    cs[tid] = 0.f;
    __syncthreads();

    float col_acc[8] = {0, 0, 0, 0, 0, 0, 0, 0};
    float sq_acc = 0.f;

    int rbase = blockIdx.x * 64 + wid * 8;
    for (int rr = 0; rr < 8; rr++) {
        int row = rbase + rr;
        const float4* p4 = (const float4*)row_ptr(src, tgt, row);
        float s = 0.f;
#pragma unroll
        for (int t = 0; t < 2; t++) {
            float4 v = p4[lane + t * 32];
            float x[4] = {v.x, v.y, v.z, v.w};
            uint32_t hb[4], lb[4];
#pragma unroll
            for (int k = 0; k < 4; k++) {
                s += x[k] * x[k];
                col_acc[t * 4 + k] += x[k];
                __half h = __float2half_rn(x[k]);
                float r = x[k] - __half2float(h);
                __half l = __float2half_rn(r);
                hb[k] = (uint32_t)__half_as_ushort(h);
                lb[k] = (uint32_t)__half_as_ushort(l);
            }
            size_t q = (size_t)row * 64 + lane + t * 32;   // uint2 index (4 halves)
            ((uint2*)g_hi)[q] = make_uint2(hb[0] | (hb[1] << 16), hb[2] | (hb[3] << 16));
            ((uint2*)g_lo)[q] = make_uint2(lb[0] | (lb[1] << 16), lb[2] | (lb[3] << 16));
        }
#pragma unroll
        for (int o = 16; o > 0; o >>= 1) s += __shfl_xor_sync(0xffffffffu, s, o);
        if (lane == 0) { g_sq[row] = s; sq_acc += s; }
    }
    if (lane == 0) atomicAdd(&g_sumsq, (double)sq_acc);

#pragma unroll
    for (int t = 0; t < 2; t++)
#pragma unroll
        for (int k = 0; k < 4; k++)
            atomicAdd(&cs[t * 128 + lane * 4 + k], col_acc[t * 4 + k]);
    __syncthreads();
    atomicAdd(&g_colsum[tid], (double)cs[tid]);
}

__global__ void finalize_kernel() {
    __shared__ double red[DIM];
    int t = threadIdx.x;
    double c = g_colsum[t];
    red[t] = c * c;
    __syncthreads();
    for (int o = 128; o > 0; o >>= 1) {
        if (t < o) red[t] += red[t + o];
        __syncthreads();
    }
    if (t == 0) {
        double n = (double)NPTS;
        double sumL2 = 2.0 * n * g_sumsq - 2.0 * red[0];
        double bw = sumL2 / (n * n - n) / 4.0;   // / KERNEL_MUL^(KERNEL_NUM//2)
        g_c = (float)(-1.0 / (16.0 * bw * 0.6931471805599453));
    }
}

// ---------------------------------------------------------------- main tile kernel
// 512 threads, 16 warps in a 4x4 grid; warp tile 32x32; CTA tile 128x128.
// smem arrays per stage: A_hi, B_hi, B_lo; each 128 rows x 80B (32 fp16 + pad)
#define STRIDE_B    80
#define ARR_BYTES   (128 * STRIDE_B)        // 10240
#define STAGE_BYTES (3 * ARR_BYTES)         // 30720
#define NSTAGE      3
#define DYN_SMEM    (NSTAGE * STAGE_BYTES)  // 92160

__global__ void __launch_bounds__(512, 1)
mmd_mma_kernel() {
    extern __shared__ char dsmem[];
    __shared__ float red[512];
    __shared__ float sqa_s[TILE];
    __shared__ float sqb_s[TILE];

    uint32_t dyn_u = smem_u32(dsmem);
    int tid  = threadIdx.x;
    int wid  = tid >> 5;
    int lane = tid & 31;
    int wm   = wid & 3;       // 4 warp-rows of 32
    int wn   = wid >> 2;      // 4 warp-cols of 32

    // decode linear block id -> (bi, bj), bi <= bj
    int b = blockIdx.x;
    float fb = (float)b;
    int bi = (int)((2.0f * NT + 1.0f - sqrtf((2.0f * NT + 1.0f) * (2.0f * NT + 1.0f) - 8.0f * fb)) * 0.5f);
    if (bi < 0) bi = 0;
    if (bi >= NT) bi = NT - 1;
#define TRI_START(i) ((i) * NT - (i) * ((i) - 1) / 2)
    while (bi + 1 < NT && TRI_START(bi + 1) <= b) bi++;
    while (bi > 0 && TRI_START(bi) > b) bi--;
    int bj = bi + (b - TRI_START(bi));
#undef TRI_START
    int row0 = bi * TILE;
    int col0 = bj * TILE;

    if (tid < TILE) {
        sqa_s[tid] = g_sq[row0 + tid];
        sqb_s[tid] = g_sq[col0 + tid];
    }

    const char* gbase[3];
    gbase[0] = (const char*)(g_hi + (size_t)row0 * DIM);   // A_hi
    gbase[1] = (const char*)(g_hi + (size_t)col0 * DIM);   // B_hi
    gbase[2] = (const char*)(g_lo + (size_t)col0 * DIM);   // B_lo

    float acc[2][4][4];
#pragma unroll
    for (int mi = 0; mi < 2; mi++)
#pragma unroll
        for (int ni = 0; ni < 4; ni++)
#pragma unroll
            for (int e = 0; e < 4; e++) acc[mi][ni][e] = 0.f;

    // loader: 1536 x 16B per chunk; 512 threads -> 3 each (one per array)
    int l_row = tid >> 2;
    int l_q   = tid & 3;
#define ISSUE_LOADS(c, s) do { \
    _Pragma("unroll") \
    for (int arr = 0; arr < 3; arr++) { \
        const char* srcp = gbase[arr] + (size_t)l_row * 512 + (c) * 64 + l_q * 16; \
        uint32_t dst = dyn_u + (s) * STAGE_BYTES + arr * ARR_BYTES + l_row * STRIDE_B + l_q * 16; \
        CP_ASYNC16(dst, srcp); \
    } \
    CP_COMMIT(); \
} while (0)

    // ldmatrix lane-address components
    int a_m    = lane >> 3;
    int a_rofs = ((a_m & 1) << 3) + (lane & 7);
    int a_koff = (a_m >> 1) << 4;
    int b_nofs = ((a_m >> 1) << 3) + (lane & 7);
    int b_koff = (a_m & 1) << 4;

    ISSUE_LOADS(0, 0);
    ISSUE_LOADS(1, 1);

    for (int c = 0; c < 8; c++) {
        int s = c % NSTAGE;
        CP_WAIT1();
        __syncthreads();
        if (c + 2 < 8) ISSUE_LOADS(c + 2, (c + 2) % NSTAGE);

        uint32_t stage_u = dyn_u + s * STAGE_BYTES;
#pragma unroll
        for (int ks = 0; ks < 2; ks++) {
            uint32_t Ah[2][4], Bh[2][4], Bl[2][4];
#pragma unroll
            for (int mi = 0; mi < 2; mi++) {
                int r = wm * 32 + mi * 16 + a_rofs;
                uint32_t ad = stage_u + r * STRIDE_B + ks * 32 + a_koff;
                LDSM_X4(Ah[mi][0], Ah[mi][1], Ah[mi][2], Ah[mi][3], ad);
            }
#pragma unroll
            for (int pi = 0; pi < 2; pi++) {
                int nl = wn * 32 + pi * 16 + b_nofs;
                uint32_t bd = stage_u + ARR_BYTES + nl * STRIDE_B + ks * 32 + b_koff;
                LDSM_X4(Bh[pi][0], Bh[pi][1], Bh[pi][2], Bh[pi][3], bd);
                LDSM_X4(Bl[pi][0], Bl[pi][1], Bl[pi][2], Bl[pi][3], bd + ARR_BYTES);
            }
#pragma unroll
            for (int mi = 0; mi < 2; mi++) {
#pragma unroll
                for (int ni = 0; ni < 4; ni++) {
                    int pi = ni >> 1, h = (ni & 1) * 2;
                    MMA_F16(acc[mi][ni], Ah[mi], Bh[pi][h], Bh[pi][h + 1]);
                    MMA_F16(acc[mi][ni], Ah[mi], Bl[pi][h], Bl[pi][h + 1]);
                }
            }
        }
        __syncthreads();   // stage s free for refill
    }

    // epilogue: row = wm*32+mi*16 + lane/4 + (e>=2)*8 ; col = wn*32+ni*8 + (lane%4)*2 + (e&1)
    float cexp = g_c;
    int rlo = lane >> 2;
    int cl0 = (lane & 3) * 2;
    float s = 0.f;
#pragma unroll
    for (int mi = 0; mi < 2; mi++) {
        float sqr0 = sqa_s[wm * 32 + mi * 16 + rlo];
        float sqr1 = sqa_s[wm * 32 + mi * 16 + rlo + 8];
#pragma unroll
        for (int ni = 0; ni < 4; ni++) {
            float sqc0 = sqb_s[wn * 32 + ni * 8 + cl0];
            float sqc1 = sqb_s[wn * 32 + ni * 8 + cl0 + 1];
#pragma unroll
            for (int e = 0; e < 4; e++) {
                float sr = (e >= 2) ? sqr1 : sqr0;
                float sc = (e & 1) ? sqc1 : sqc0;
                float L2 = fmaxf(sr + sc - 2.f * acc[mi][ni][e], 0.f);
                float u;
                asm("ex2.approx.ftz.f32 %0, %1;" : "=f"(u) : "f"(L2 * cexp));
                float u2 = u * u, u4 = u2 * u2, u8 = u4 * u4;
                s += u + u2 + u4 + u8 + u8 * u8;
            }
        }
    }

    red[tid] = s;
    __syncthreads();
#pragma unroll
    for (int o = 256; o > 0; o >>= 1) {
        if (tid < o) red[tid] += red[tid + o];
        __syncthreads();
    }
    if (tid == 0) {
        float w  = (bi == bj) ? 1.f : 2.f;
        float sr = (row0 < NSRC) ? 1.f : -1.f;
        float sc = (col0 < NSRC) ? 1.f : -1.f;
        atomicAdd(&g_acc, (double)(red[0] * w * sr * sc));
    }
}

__global__ void writeout_kernel(float* out) {
    out[0] = (float)(g_acc / ((double)NSRC * (double)NSRC));
}

// ---------------------------------------------------------------- launch
extern "C" void kernel_launch(void* const* d_in, const int* in_sizes, int n_in,
                              void* d_out, int out_size) {
    const float* src = (const float*)d_in[0];
    const float* tgt = (const float*)d_in[1];
    float* out = (float*)d_out;

    cudaFuncSetAttribute(mmd_mma_kernel, cudaFuncAttributeMaxDynamicSharedMemorySize, DYN_SMEM);

    zero_kernel<<<1, 256>>>();
    prep_kernel<<<NPTS / 64, 256>>>(src, tgt);     // split + norms + colsums fused
    finalize_kernel<<<1, 256>>>();
    mmd_mma_kernel<<<NBLK, 512, DYN_SMEM>>>();
    writeout_kernel<<<1, 1>>>(out);
}

// round 7
// speedup vs baseline: 1.4404x; 1.3094x over previous
#include <cuda_runtime.h>
#include <cuda_fp16.h>
#include <math.h>
#include <stdint.h>

#define NPTS 8192
#define NSRC 4096
#define DIM  256
#define TILE 128
#define NT   (NPTS / TILE)          // 64
#define NBLK (NT * (NT + 1) / 2)    // 2080 upper-triangle tile pairs

// ---------------------------------------------------------------- scratch
__device__ float  g_sq[NPTS];
__device__ double g_colsum[DIM];
__device__ double g_sumsq;
__device__ float  g_c;              // exp2 scale: -1/(16*bw'*ln2)
__device__ double g_acc;
__device__ __half g_hi[NPTS * DIM];
__device__ __half g_lo[NPTS * DIM];

// ---------------------------------------------------------------- helpers
__device__ __forceinline__ uint32_t smem_u32(const void* p) {
    uint32_t a;
    asm("{ .reg .u64 t; cvta.to.shared.u64 t, %1; cvt.u32.u64 %0, t; }" : "=r"(a) : "l"(p));
    return a;
}
#define CP_ASYNC16(dst, src) \
    asm volatile("cp.async.ca.shared.global [%0], [%1], 16;" :: "r"(dst), "l"(src))
#define CP_COMMIT() asm volatile("cp.async.commit_group;" ::: "memory")
#define CP_WAIT1()  asm volatile("cp.async.wait_group 1;" ::: "memory")

#define LDSM_X4(r0, r1, r2, r3, a) \
    asm volatile("ldmatrix.sync.aligned.m8n8.x4.shared.b16 {%0,%1,%2,%3}, [%4];" \
        : "=r"(r0), "=r"(r1), "=r"(r2), "=r"(r3) : "r"(a))

#define MMA_F16(d, a, b0, b1) \
    asm volatile("mma.sync.aligned.m16n8k16.row.col.f32.f16.f16.f32 " \
        "{%0,%1,%2,%3}, {%4,%5,%6,%7}, {%8,%9}, {%0,%1,%2,%3};" \
        : "+f"((d)[0]), "+f"((d)[1]), "+f"((d)[2]), "+f"((d)[3]) \
        : "r"((a)[0]), "r"((a)[1]), "r"((a)[2]), "r"((a)[3]), "r"(b0), "r"(b1))

__device__ __forceinline__ const float* row_ptr(const float* src, const float* tgt, int i) {
    return (i < NSRC) ? (src + (size_t)i * DIM) : (tgt + (size_t)(i - NSRC) * DIM);
}

// ---------------------------------------------------------------- prep kernels
__global__ void zero_kernel() {
    int t = threadIdx.x;
    if (t < DIM) g_colsum[t] = 0.0;
    if (t == 0) { g_sumsq = 0.0; g_acc = 0.0; }
}

// 128 blocks x 256 threads; block handles 64 rows (warp -> 8 rows).
// Fused: fp16 hi/lo split + per-row ||x||^2 + column sums.
__global__ void prep_kernel(const float* __restrict__ src, const float* __restrict__ tgt) {
    __shared__ float cs[DIM];
    int tid  = threadIdx.x;
    int wid  = tid >> 5;
    int lane = tid & 31;
    cs[tid] = 0.f;
    __syncthreads();

    float col_acc[8] = {0, 0, 0, 0, 0, 0, 0, 0};
    float sq_acc = 0.f;

    int rbase = blockIdx.x * 64 + wid * 8;
    for (int rr = 0; rr < 8; rr++) {
        int row = rbase + rr;
        const float4* p4 = (const float4*)row_ptr(src, tgt, row);
        float s = 0.f;
#pragma unroll
        for (int t = 0; t < 2; t++) {
            float4 v = p4[lane + t * 32];
            float x[4] = {v.x, v.y, v.z, v.w};
            uint32_t hb[4], lb[4];
#pragma unroll
            for (int k = 0; k < 4; k++) {
                s += x[k] * x[k];
                col_acc[t * 4 + k] += x[k];
                __half h = __float2half_rn(x[k]);
                float r = x[k] - __half2float(h);
                __half l = __float2half_rn(r);
                hb[k] = (uint32_t)__half_as_ushort(h);
                lb[k] = (uint32_t)__half_as_ushort(l);
            }
            size_t q = (size_t)row * 64 + lane + t * 32;   // uint2 index (4 halves)
            ((uint2*)g_hi)[q] = make_uint2(hb[0] | (hb[1] << 16), hb[2] | (hb[3] << 16));
            ((uint2*)g_lo)[q] = make_uint2(lb[0] | (lb[1] << 16), lb[2] | (lb[3] << 16));
        }
#pragma unroll
        for (int o = 16; o > 0; o >>= 1) s += __shfl_xor_sync(0xffffffffu, s, o);
        if (lane == 0) { g_sq[row] = s; sq_acc += s; }
    }
    if (lane == 0) atomicAdd(&g_sumsq, (double)sq_acc);

#pragma unroll
    for (int t = 0; t < 2; t++)
#pragma unroll
        for (int k = 0; k < 4; k++)
            atomicAdd(&cs[t * 128 + lane * 4 + k], col_acc[t * 4 + k]);
    __syncthreads();
    atomicAdd(&g_colsum[tid], (double)cs[tid]);
}

__global__ void finalize_kernel() {
    __shared__ double red[DIM];
    int t = threadIdx.x;
    double c = g_colsum[t];
    red[t] = c * c;
    __syncthreads();
    for (int o = 128; o > 0; o >>= 1) {
        if (t < o) red[t] += red[t + o];
        __syncthreads();
    }
    if (t == 0) {
        double n = (double)NPTS;
        double sumL2 = 2.0 * n * g_sumsq - 2.0 * red[0];
        double bw = sumL2 / (n * n - n) / 4.0;   // / KERNEL_MUL^(KERNEL_NUM//2)
        g_c = (float)(-1.0 / (16.0 * bw * 0.6931471805599453));
    }
}

// ---------------------------------------------------------------- main tile kernel
// 256 threads, 8 warps (2x4), warp tile 64x32, CTA tile 128x128; 2 CTAs/SM.
// smem arrays per stage: A_hi, B_hi, B_lo; each 128 rows x 80B (32 fp16 + pad)
#define STRIDE_B    80
#define ARR_BYTES   (128 * STRIDE_B)        // 10240
#define STAGE_BYTES (3 * ARR_BYTES)         // 30720
#define NSTAGE      3
#define DYN_SMEM    (NSTAGE * STAGE_BYTES)  // 92160

__global__ void __launch_bounds__(256, 2)
mmd_mma_kernel() {
    extern __shared__ char dsmem[];
    __shared__ float red[256];
    __shared__ float sqa_s[TILE];
    __shared__ float sqb_s[TILE];

    uint32_t dyn_u = smem_u32(dsmem);
    int tid  = threadIdx.x;
    int wid  = tid >> 5;
    int lane = tid & 31;
    int wm   = wid & 1;       // 2 warp-rows of 64
    int wn   = wid >> 1;      // 4 warp-cols of 32

    // decode linear block id -> (bi, bj), bi <= bj
    int b = blockIdx.x;
    float fb = (float)b;
    int bi = (int)((2.0f * NT + 1.0f - sqrtf((2.0f * NT + 1.0f) * (2.0f * NT + 1.0f) - 8.0f * fb)) * 0.5f);
    if (bi < 0) bi = 0;
    if (bi >= NT) bi = NT - 1;
#define TRI_START(i) ((i) * NT - (i) * ((i) - 1) / 2)
    while (bi + 1 < NT && TRI_START(bi + 1) <= b) bi++;
    while (bi > 0 && TRI_START(bi) > b) bi--;
    int bj = bi + (b - TRI_START(bi));
#undef TRI_START
    int row0 = bi * TILE;
    int col0 = bj * TILE;

    if (tid < TILE) {
        sqa_s[tid] = g_sq[row0 + tid];
        sqb_s[tid] = g_sq[col0 + tid];
    }

    const char* gbase[3];
    gbase[0] = (const char*)(g_hi + (size_t)row0 * DIM);   // A_hi
    gbase[1] = (const char*)(g_hi + (size_t)col0 * DIM);   // B_hi
    gbase[2] = (const char*)(g_lo + (size_t)col0 * DIM);   // B_lo

    float acc[4][4][4];
#pragma unroll
    for (int mi = 0; mi < 4; mi++)
#pragma unroll
        for (int ni = 0; ni < 4; ni++)
#pragma unroll
            for (int e = 0; e < 4; e++) acc[mi][ni][e] = 0.f;

    // loader: 1536 x 16B per chunk; 256 threads -> 6 each
#define ISSUE_LOADS(c, s) do { \
    _Pragma("unroll") \
    for (int i = 0; i < 6; i++) { \
        int arr = i >> 1; \
        int rem = tid + (i & 1) * 256;      /* 0..511 */ \
        int row = rem >> 2; \
        int q   = rem & 3; \
        const char* srcp = gbase[arr] + (size_t)row * 512 + (c) * 64 + q * 16; \
        uint32_t dst = dyn_u + (s) * STAGE_BYTES + arr * ARR_BYTES + row * STRIDE_B + q * 16; \
        CP_ASYNC16(dst, srcp); \
    } \
    CP_COMMIT(); \
} while (0)

    // ldmatrix lane-address components
    int a_m    = lane >> 3;
    int a_rofs = ((a_m & 1) << 3) + (lane & 7);
    int a_koff = (a_m >> 1) << 4;
    int b_nofs = ((a_m >> 1) << 3) + (lane & 7);
    int b_koff = (a_m & 1) << 4;

    ISSUE_LOADS(0, 0);
    ISSUE_LOADS(1, 1);

    for (int c = 0; c < 8; c++) {
        int s = c % NSTAGE;
        CP_WAIT1();
        __syncthreads();      // also protects stage (c+2)%3: all warps past chunk c-1 compute
        if (c + 2 < 8) ISSUE_LOADS(c + 2, (c + 2) % NSTAGE);

        uint32_t stage_u = dyn_u + s * STAGE_BYTES;
#pragma unroll
        for (int ks = 0; ks < 2; ks++) {
            uint32_t Ah[4][4], Bh[2][4], Bl[2][4];
#pragma unroll
            for (int mi = 0; mi < 4; mi++) {
                int r = wm * 64 + mi * 16 + a_rofs;
                uint32_t ad = stage_u + r * STRIDE_B + ks * 32 + a_koff;
                LDSM_X4(Ah[mi][0], Ah[mi][1], Ah[mi][2], Ah[mi][3], ad);
            }
#pragma unroll
            for (int pi = 0; pi < 2; pi++) {
                int nl = wn * 32 + pi * 16 + b_nofs;
                uint32_t bd = stage_u + ARR_BYTES + nl * STRIDE_B + ks * 32 + b_koff;
                LDSM_X4(Bh[pi][0], Bh[pi][1], Bh[pi][2], Bh[pi][3], bd);
                LDSM_X4(Bl[pi][0], Bl[pi][1], Bl[pi][2], Bl[pi][3], bd + ARR_BYTES);
            }
#pragma unroll
            for (int mi = 0; mi < 4; mi++) {
#pragma unroll
                for (int ni = 0; ni < 4; ni++) {
                    int pi = ni >> 1, h = (ni & 1) * 2;
                    MMA_F16(acc[mi][ni], Ah[mi], Bh[pi][h], Bh[pi][h + 1]);
                    MMA_F16(acc[mi][ni], Ah[mi], Bl[pi][h], Bl[pi][h + 1]);
                }
            }
        }
        // no trailing sync: next chunk's top barrier orders reads before refill
    }

    // epilogue: row = wm*64+mi*16 + lane/4 + (e>=2)*8 ; col = wn*32+ni*8 + (lane%4)*2 + (e&1)
    float cexp = g_c;
    int rlo = lane >> 2;
    int cl0 = (lane & 3) * 2;
    float s = 0.f;
#pragma unroll
    for (int mi = 0; mi < 4; mi++) {
        float sqr0 = sqa_s[wm * 64 + mi * 16 + rlo];
        float sqr1 = sqa_s[wm * 64 + mi * 16 + rlo + 8];
#pragma unroll
        for (int ni = 0; ni < 4; ni++) {
            float sqc0 = sqb_s[wn * 32 + ni * 8 + cl0];
            float sqc1 = sqb_s[wn * 32 + ni * 8 + cl0 + 1];
#pragma unroll
            for (int e = 0; e < 4; e++) {
                float sr = (e >= 2) ? sqr1 : sqr0;
                float sc = (e & 1) ? sqc1 : sqc0;
                float L2 = fmaxf(sr + sc - 2.f * acc[mi][ni][e], 0.f);
                float u;
                asm("ex2.approx.ftz.f32 %0, %1;" : "=f"(u) : "f"(L2 * cexp));
                float u2 = u * u, u4 = u2 * u2, u8 = u4 * u4;
                s += u + u2 + u4 + u8 + u8 * u8;
            }
        }
    }

    __syncthreads();          // mainloop done in all warps before red[] reuse
    red[tid] = s;
    __syncthreads();
#pragma unroll
    for (int o = 128; o > 0; o >>= 1) {
        if (tid < o) red[tid] += red[tid + o];
        __syncthreads();
    }
    if (tid == 0) {
        float w  = (bi == bj) ? 1.f : 2.f;
        float sr = (row0 < NSRC) ? 1.f : -1.f;
        float sc = (col0 < NSRC) ? 1.f : -1.f;
        atomicAdd(&g_acc, (double)(red[0] * w * sr * sc));
    }
}

__global__ void writeout_kernel(float* out) {
    out[0] = (float)(g_acc / ((double)NSRC * (double)NSRC));
}

// ---------------------------------------------------------------- launch
extern "C" void kernel_launch(void* const* d_in, const int* in_sizes, int n_in,
                              void* d_out, int out_size) {
    const float* src = (const float*)d_in[0];
    const float* tgt = (const float*)d_in[1];
    float* out = (float*)d_out;

    cudaFuncSetAttribute(mmd_mma_kernel, cudaFuncAttributeMaxDynamicSharedMemorySize, DYN_SMEM);

    zero_kernel<<<1, 256>>>();
    prep_kernel<<<NPTS / 64, 256>>>(src, tgt);     // split + norms + colsums fused
    finalize_kernel<<<1, 256>>>();
    mmd_mma_kernel<<<NBLK, 256, DYN_SMEM>>>();
    writeout_kernel<<<1, 1>>>(out);
}